// round 16
// baseline (speedup 1.0000x reference)
#include <cuda_runtime.h>

// Fused cosine-score attention, single query. Two kernels.
//
// stage1: SMEM-accumulator variant to double occupancy. All previous
//   variants ran 16 warps/SM (register-bound: q+kv+acc = 120 regs) giving
//   16 KB/SM of loads in flight -> the measured 5.2 TB/s plateau. Moving
//   acc (64 KB) + q (4 KB) to smem cuts the loop to ~56 regs, allowing
//   __launch_bounds__(512,2): 2 blocks/SM, 32 warps, 32 KB/SM in flight.
//   Row body otherwise identical. Block tree-reduce in smem -> 296 partials.
// stage2: 16x512 deterministic reduction (best measured config).

#define NBLK 296                   // 2 blocks per SM
#define NTHR 512
#define WPB  (NTHR / 32)           // 16 warps per block
#define NWARPS (NBLK * WPB)        // 4736
#define H 1024
#define HV4 (H / 4)                // 256 float4 per row

// Dynamic smem layout: [0,64KB) acc[16][256] float4, [64KB,68KB) q float4.
#define SMEM_BYTES (WPB * HV4 * 16 + HV4 * 16)

__device__ float4 g_partial[NBLK][HV4];   // 1.2 MB scratch

__global__ __launch_bounds__(NTHR, 2)
void bahdanau_stage1(const float* __restrict__ q,
                     const float* __restrict__ keys, int S) {
    extern __shared__ float4 smem[];
    float4* acc = smem + threadIdx.x / 32 * HV4;   // this warp's 4 KB slot
    float4* sq  = smem + WPB * HV4;                // shared q row

    const int wib  = threadIdx.x >> 5;
    const int warp = blockIdx.x * WPB + wib;
    const int lane = threadIdx.x & 31;

    // Stage q into smem; zero this warp's accumulator.
    for (int i = threadIdx.x; i < HV4; i += NTHR)
        sq[i] = ((const float4*)q)[i];
#pragma unroll
    for (int i = 0; i < 8; i++)
        acc[i * 32 + lane] = make_float4(0.f, 0.f, 0.f, 0.f);
    __syncthreads();

    // |q| from smem.
    float qss = 0.f;
#pragma unroll
    for (int i = 0; i < 8; i++) {
        float4 qv = sq[i * 32 + lane];
        qss += qv.x * qv.x + qv.y * qv.y + qv.z * qv.z + qv.w * qv.w;
    }
#pragma unroll
    for (int o = 16; o; o >>= 1) qss += __shfl_xor_sync(0xffffffffu, qss, o);
    const float inv_qn = rsqrtf(qss);

    for (int s = warp; s < S; s += NWARPS) {
        const float4* row = (const float4*)(keys + (size_t)s * H);
        float4 kv[8];
        float dot = 0.f, kss = 0.f;
#pragma unroll
        for (int i = 0; i < 8; i++) {
            kv[i] = row[i * 32 + lane];
            float4 qv = sq[i * 32 + lane];
            dot += kv[i].x * qv.x + kv[i].y * qv.y +
                   kv[i].z * qv.z + kv[i].w * qv.w;
            kss += kv[i].x * kv[i].x + kv[i].y * kv[i].y +
                   kv[i].z * kv[i].z + kv[i].w * kv[i].w;
        }
#pragma unroll
        for (int o = 16; o; o >>= 1) {
            dot += __shfl_xor_sync(0xffffffffu, dot, o);
            kss += __shfl_xor_sync(0xffffffffu, kss, o);
        }
        const float score = dot * inv_qn * rsqrtf(kss);
#pragma unroll
        for (int i = 0; i < 8; i++) {
            float4 a = acc[i * 32 + lane];
            a.x += score * kv[i].x;
            a.y += score * kv[i].y;
            a.z += score * kv[i].z;
            a.w += score * kv[i].w;
            acc[i * 32 + lane] = a;
        }
    }
    __syncthreads();

    // Tree reduction over the 16 warp slots (in smem): 16 -> 8 -> ... -> 1.
#pragma unroll
    for (int half = 8; half >= 1; half >>= 1) {
        if (wib < half) {
            const float4* src = smem + (wib + half) * HV4;
#pragma unroll
            for (int i = 0; i < 8; i++) {
                float4 a = acc[i * 32 + lane];
                float4 v = src[i * 32 + lane];
                a.x += v.x; a.y += v.y; a.z += v.z; a.w += v.w;
                acc[i * 32 + lane] = a;
            }
        }
        __syncthreads();
    }

    if (wib == 0) {
#pragma unroll
        for (int i = 0; i < 8; i++)
            g_partial[blockIdx.x][i * 32 + lane] = acc[i * 32 + lane];
    }
}

// stage2: out[h] = sum_{b<296} g_partial[b][h] (coalesced: lane -> column).
// 16 blocks x 512 threads; block owns 64 columns, 8 row-groups per column.
__global__ __launch_bounds__(512)
void bahdanau_stage2(float* __restrict__ out) {
    const int col = blockIdx.x * 64 + (threadIdx.x & 63);
    const int g   = threadIdx.x >> 6;   // 0..7
    const float* part = (const float*)g_partial;

    float s = 0.f;
#pragma unroll
    for (int b = 0; b < 37; b++) {      // 37*8 = 296 exactly
        int p = g + b * 8;
        s += part[(size_t)p * H + col];
    }

    __shared__ float sh[512];
    sh[threadIdx.x] = s;
    __syncthreads();
#pragma unroll
    for (int stride = 256; stride >= 64; stride >>= 1) {
        if (threadIdx.x < stride) sh[threadIdx.x] += sh[threadIdx.x + stride];
        __syncthreads();
    }
    if (threadIdx.x < 64) out[blockIdx.x * 64 + threadIdx.x] = sh[threadIdx.x];
}

extern "C" void kernel_launch(void* const* d_in, const int* in_sizes, int n_in,
                              void* d_out, int out_size) {
    const float* q    = (const float*)d_in[0];   // [1, 1024]
    const float* keys = (const float*)d_in[1];   // [S, 1024]
    const int S = in_sizes[1] / H;

    cudaFuncSetAttribute(bahdanau_stage1,
                         cudaFuncAttributeMaxDynamicSharedMemorySize,
                         SMEM_BYTES);
    bahdanau_stage1<<<NBLK, NTHR, SMEM_BYTES>>>(q, keys, S);
    bahdanau_stage2<<<16, 512>>>((float*)d_out);
}